// round 7
// baseline (speedup 1.0000x reference)
#include <cuda_runtime.h>

// Single-layer ReLU RNN (batch_first), h0 = 0, then out = tanh(W_out h_T + b_out).
// One thread per batch row. Hidden dim 5 padded to 6 and computed as 3 packed
// f32x2 accumulators via Blackwell fma.rn.f32x2 (halves FMA-pipe instruction
// count vs scalar FFMA). Input row streamed via double-buffered LDG.128.

typedef unsigned long long u64;

#define NIN_  3
#define NHID_ 5

__device__ __forceinline__ u64 pk2(float lo, float hi) {
    u64 r; asm("mov.b64 %0, {%1, %2};" : "=l"(r) : "f"(lo), "f"(hi)); return r;
}
__device__ __forceinline__ u64 dup2(float v) {
    u64 r; asm("mov.b64 %0, {%1, %1};" : "=l"(r) : "f"(v)); return r;
}
__device__ __forceinline__ u64 fma2_(u64 a, u64 b, u64 c) {
    u64 d; asm("fma.rn.f32x2 %0, %1, %2, %3;" : "=l"(d) : "l"(a), "l"(b), "l"(c)); return d;
}
__device__ __forceinline__ float lo2(u64 v) { return __uint_as_float((unsigned)v); }
__device__ __forceinline__ float hi2(u64 v) { return __uint_as_float((unsigned)(v >> 32)); }

struct WPack {
    u64 wi[NIN_][3];   // input weights: [input i][hidden pair p] = (W_ih[2p][i], W_ih[2p+1][i])
    u64 wh[NHID_][3];  // recurrent:     [hidden k][pair p]       = (W_hh[2p][k], W_hh[2p+1][k])
    u64 bias[3];       // b_ih + b_hh, packed over hidden pairs (pad = 0)
};

__device__ __forceinline__ void rnn_step(float x0, float x1, float x2,
                                         const WPack& W, u64 hd[NHID_]) {
    u64 a0 = W.bias[0], a1 = W.bias[1], a2 = W.bias[2];
    u64 d;
    d = dup2(x0);
    a0 = fma2_(d, W.wi[0][0], a0); a1 = fma2_(d, W.wi[0][1], a1); a2 = fma2_(d, W.wi[0][2], a2);
    d = dup2(x1);
    a0 = fma2_(d, W.wi[1][0], a0); a1 = fma2_(d, W.wi[1][1], a1); a2 = fma2_(d, W.wi[1][2], a2);
    d = dup2(x2);
    a0 = fma2_(d, W.wi[2][0], a0); a1 = fma2_(d, W.wi[2][1], a1); a2 = fma2_(d, W.wi[2][2], a2);
#pragma unroll
    for (int k = 0; k < NHID_; ++k) {
        a0 = fma2_(hd[k], W.wh[k][0], a0);
        a1 = fma2_(hd[k], W.wh[k][1], a1);
        a2 = fma2_(hd[k], W.wh[k][2], a2);
    }
    // relu + re-duplicate each hidden scalar into both halves for next step
    hd[0] = dup2(fmaxf(lo2(a0), 0.f));
    hd[1] = dup2(fmaxf(hi2(a0), 0.f));
    hd[2] = dup2(fmaxf(lo2(a1), 0.f));
    hd[3] = dup2(fmaxf(hi2(a1), 0.f));
    hd[4] = dup2(fmaxf(lo2(a2), 0.f));
    // hi half of a2 is the padded (zero-weight) hidden unit; never read.
}

// 16 timesteps = 48 floats = 12 float4 from the register buffer.
__device__ __forceinline__ void steps16(const float4 (&bf)[12], const WPack& W, u64 hd[NHID_]) {
#pragma unroll
    for (int g = 0; g < 4; ++g) {
        float4 p = bf[3*g + 0];
        float4 q = bf[3*g + 1];
        float4 r = bf[3*g + 2];
        rnn_step(p.x, p.y, p.z, W, hd);
        rnn_step(p.w, q.x, q.y, W, hd);
        rnn_step(q.z, q.w, r.x, W, hd);
        rnn_step(r.y, r.z, r.w, W, hd);
    }
}

__global__ void __launch_bounds__(32, 1) rnn_scan_kernel(
    const float* __restrict__ state,
    const float* __restrict__ W_ih, const float* __restrict__ W_hh,
    const float* __restrict__ b_ih, const float* __restrict__ b_hh,
    const float* __restrict__ W_out, const float* __restrict__ b_out,
    float* __restrict__ out, int B, int T)
{
    int b = blockIdx.x * 32 + threadIdx.x;
    if (b >= B) return;

    // ---- Build packed weights in registers (uniform across threads; L1/L2 broadcast) ----
    WPack W;
#pragma unroll
    for (int p = 0; p < 3; ++p) {
        const int j0 = 2*p, j1 = 2*p + 1;
        const float bl = (j0 < NHID_) ? (b_ih[j0] + b_hh[j0]) : 0.f;
        const float bh = (j1 < NHID_) ? (b_ih[j1] + b_hh[j1]) : 0.f;
        W.bias[p] = pk2(bl, bh);
#pragma unroll
        for (int i = 0; i < NIN_; ++i) {
            const float wl = (j0 < NHID_) ? W_ih[j0*NIN_ + i] : 0.f;
            const float wh = (j1 < NHID_) ? W_ih[j1*NIN_ + i] : 0.f;
            W.wi[i][p] = pk2(wl, wh);
        }
#pragma unroll
        for (int k = 0; k < NHID_; ++k) {
            const float wl = (j0 < NHID_) ? W_hh[j0*NHID_ + k] : 0.f;
            const float wh = (j1 < NHID_) ? W_hh[j1*NHID_ + k] : 0.f;
            W.wh[k][p] = pk2(wl, wh);
        }
    }

    u64 hd[NHID_];
#pragma unroll
    for (int k = 0; k < NHID_; ++k) hd[k] = dup2(0.f);

    const float* row = state + (size_t)b * (size_t)T * NIN_;

    if ((T & 3) == 0) {
        // Fast path: row base is 16B-aligned (T % 4 == 0 -> 12*T % 16 == 0).
        const float4* xr = reinterpret_cast<const float4*>(row);
        const int NC = T / 16;           // 16-step chunks, 12 float4 each
        float4 A[12], Bb[12];
        if (NC > 0) {
#pragma unroll
            for (int i = 0; i < 12; ++i) A[i] = xr[i];
        }
        int c = 0;
        while (c < NC) {
            if (c + 1 < NC) {
#pragma unroll
                for (int i = 0; i < 12; ++i) Bb[i] = xr[(size_t)(c + 1) * 12 + i];
            }
            steps16(A, W, hd);
            if (c + 2 < NC) {
#pragma unroll
                for (int i = 0; i < 12; ++i) A[i] = xr[(size_t)(c + 2) * 12 + i];
            }
            if (c + 1 < NC) steps16(Bb, W, hd);
            c += 2;
        }
        // Remainder steps (T % 16), scalar loads.
        for (int t = NC * 16; t < T; ++t)
            rnn_step(row[3*t + 0], row[3*t + 1], row[3*t + 2], W, hd);
    } else {
        // Generic fallback (unused for T=2048): scalar loads each step.
        for (int t = 0; t < T; ++t)
            rnn_step(row[3*t + 0], row[3*t + 1], row[3*t + 2], W, hd);
    }

    // ---- out = tanh(W_out . h_T + b_out), NOUT = 1 ----
    const float h0 = lo2(hd[0]), h1 = lo2(hd[1]), h2 = lo2(hd[2]);
    const float h3 = lo2(hd[3]), h4 = lo2(hd[4]);
    float acc = b_out[0];
    acc = fmaf(h0, W_out[0],
          fmaf(h1, W_out[1],
          fmaf(h2, W_out[2],
          fmaf(h3, W_out[3],
          fmaf(h4, W_out[4], acc)))));
    out[b] = tanhf(acc);
}

extern "C" void kernel_launch(void* const* d_in, const int* in_sizes, int n_in,
                              void* d_out, int out_size) {
    const float* state = (const float*)d_in[0];   // [B, T, 3]
    const float* W_ih  = (const float*)d_in[1];   // [5, 3]
    const float* W_hh  = (const float*)d_in[2];   // [5, 5]
    const float* b_ih  = (const float*)d_in[3];   // [5]
    const float* b_hh  = (const float*)d_in[4];   // [5]
    const float* W_out = (const float*)d_in[5];   // [1, 5]
    const float* b_out = (const float*)d_in[6];   // [1]

    const int B = out_size;                       // NOUT == 1
    const int T = in_sizes[0] / (B * NIN_);

    const int blocks = (B + 31) / 32;             // 1-warp blocks -> spread across SMs
    rnn_scan_kernel<<<blocks, 32>>>(state, W_ih, W_hh, b_ih, b_hh, W_out, b_out,
                                    (float*)d_out, B, T);
}

// round 8
// speedup vs baseline: 1.0196x; 1.0196x over previous
#include <cuda_runtime.h>

// Single-layer ReLU RNN (batch_first), h0 = 0, then out = tanh(W_out h_T + b_out).
// One thread per batch row. Hidden dim 5 padded to 6 and computed as 3 packed
// f32x2 accumulators via Blackwell fma.rn.f32x2 (halves FMA-pipe instruction
// count vs scalar FFMA). Input row streamed via double-buffered LDG.128.

typedef unsigned long long u64;

#define NIN_  3
#define NHID_ 5

__device__ __forceinline__ u64 pk2(float lo, float hi) {
    u64 r; asm("mov.b64 %0, {%1, %2};" : "=l"(r) : "f"(lo), "f"(hi)); return r;
}
__device__ __forceinline__ u64 dup2(float v) {
    u64 r; asm("mov.b64 %0, {%1, %1};" : "=l"(r) : "f"(v)); return r;
}
__device__ __forceinline__ u64 fma2_(u64 a, u64 b, u64 c) {
    u64 d; asm("fma.rn.f32x2 %0, %1, %2, %3;" : "=l"(d) : "l"(a), "l"(b), "l"(c)); return d;
}
__device__ __forceinline__ float lo2(u64 v) { return __uint_as_float((unsigned)v); }
__device__ __forceinline__ float hi2(u64 v) { return __uint_as_float((unsigned)(v >> 32)); }

struct WPack {
    u64 wi[NIN_][3];   // input weights: [input i][hidden pair p] = (W_ih[2p][i], W_ih[2p+1][i])
    u64 wh[NHID_][3];  // recurrent:     [hidden k][pair p]       = (W_hh[2p][k], W_hh[2p+1][k])
    u64 bias[3];       // b_ih + b_hh, packed over hidden pairs (pad = 0)
};

__device__ __forceinline__ void rnn_step(float x0, float x1, float x2,
                                         const WPack& W, u64 hd[NHID_]) {
    u64 a0 = W.bias[0], a1 = W.bias[1], a2 = W.bias[2];
    u64 d;
    d = dup2(x0);
    a0 = fma2_(d, W.wi[0][0], a0); a1 = fma2_(d, W.wi[0][1], a1); a2 = fma2_(d, W.wi[0][2], a2);
    d = dup2(x1);
    a0 = fma2_(d, W.wi[1][0], a0); a1 = fma2_(d, W.wi[1][1], a1); a2 = fma2_(d, W.wi[1][2], a2);
    d = dup2(x2);
    a0 = fma2_(d, W.wi[2][0], a0); a1 = fma2_(d, W.wi[2][1], a1); a2 = fma2_(d, W.wi[2][2], a2);
#pragma unroll
    for (int k = 0; k < NHID_; ++k) {
        a0 = fma2_(hd[k], W.wh[k][0], a0);
        a1 = fma2_(hd[k], W.wh[k][1], a1);
        a2 = fma2_(hd[k], W.wh[k][2], a2);
    }
    // relu + re-duplicate each hidden scalar into both halves for next step
    hd[0] = dup2(fmaxf(lo2(a0), 0.f));
    hd[1] = dup2(fmaxf(hi2(a0), 0.f));
    hd[2] = dup2(fmaxf(lo2(a1), 0.f));
    hd[3] = dup2(fmaxf(hi2(a1), 0.f));
    hd[4] = dup2(fmaxf(lo2(a2), 0.f));
    // hi half of a2 is the padded (zero-weight) hidden unit; never read.
}

// 16 timesteps = 48 floats = 12 float4 from the register buffer.
__device__ __forceinline__ void steps16(const float4 (&bf)[12], const WPack& W, u64 hd[NHID_]) {
#pragma unroll
    for (int g = 0; g < 4; ++g) {
        float4 p = bf[3*g + 0];
        float4 q = bf[3*g + 1];
        float4 r = bf[3*g + 2];
        rnn_step(p.x, p.y, p.z, W, hd);
        rnn_step(p.w, q.x, q.y, W, hd);
        rnn_step(q.z, q.w, r.x, W, hd);
        rnn_step(r.y, r.z, r.w, W, hd);
    }
}

__global__ void __launch_bounds__(32, 1) rnn_scan_kernel(
    const float* __restrict__ state,
    const float* __restrict__ W_ih, const float* __restrict__ W_hh,
    const float* __restrict__ b_ih, const float* __restrict__ b_hh,
    const float* __restrict__ W_out, const float* __restrict__ b_out,
    float* __restrict__ out, int B, int T)
{
    int b = blockIdx.x * 32 + threadIdx.x;
    if (b >= B) return;

    // ---- Build packed weights in registers (uniform across threads; L1/L2 broadcast) ----
    WPack W;
#pragma unroll
    for (int p = 0; p < 3; ++p) {
        const int j0 = 2*p, j1 = 2*p + 1;
        const float bl = (j0 < NHID_) ? (b_ih[j0] + b_hh[j0]) : 0.f;
        const float bh = (j1 < NHID_) ? (b_ih[j1] + b_hh[j1]) : 0.f;
        W.bias[p] = pk2(bl, bh);
#pragma unroll
        for (int i = 0; i < NIN_; ++i) {
            const float wl = (j0 < NHID_) ? W_ih[j0*NIN_ + i] : 0.f;
            const float wh = (j1 < NHID_) ? W_ih[j1*NIN_ + i] : 0.f;
            W.wi[i][p] = pk2(wl, wh);
        }
#pragma unroll
        for (int k = 0; k < NHID_; ++k) {
            const float wl = (j0 < NHID_) ? W_hh[j0*NHID_ + k] : 0.f;
            const float wh = (j1 < NHID_) ? W_hh[j1*NHID_ + k] : 0.f;
            W.wh[k][p] = pk2(wl, wh);
        }
    }

    u64 hd[NHID_];
#pragma unroll
    for (int k = 0; k < NHID_; ++k) hd[k] = dup2(0.f);

    const float* row = state + (size_t)b * (size_t)T * NIN_;

    if ((T & 3) == 0) {
        // Fast path: row base is 16B-aligned (T % 4 == 0 -> 12*T % 16 == 0).
        const float4* xr = reinterpret_cast<const float4*>(row);
        const int NC = T / 16;           // 16-step chunks, 12 float4 each
        float4 A[12], Bb[12];
        if (NC > 0) {
#pragma unroll
            for (int i = 0; i < 12; ++i) A[i] = xr[i];
        }
        int c = 0;
        while (c < NC) {
            if (c + 1 < NC) {
#pragma unroll
                for (int i = 0; i < 12; ++i) Bb[i] = xr[(size_t)(c + 1) * 12 + i];
            }
            steps16(A, W, hd);
            if (c + 2 < NC) {
#pragma unroll
                for (int i = 0; i < 12; ++i) A[i] = xr[(size_t)(c + 2) * 12 + i];
            }
            if (c + 1 < NC) steps16(Bb, W, hd);
            c += 2;
        }
        // Remainder steps (T % 16), scalar loads.
        for (int t = NC * 16; t < T; ++t)
            rnn_step(row[3*t + 0], row[3*t + 1], row[3*t + 2], W, hd);
    } else {
        // Generic fallback (unused for T=2048): scalar loads each step.
        for (int t = 0; t < T; ++t)
            rnn_step(row[3*t + 0], row[3*t + 1], row[3*t + 2], W, hd);
    }

    // ---- out = tanh(W_out . h_T + b_out), NOUT = 1 ----
    const float h0 = lo2(hd[0]), h1 = lo2(hd[1]), h2 = lo2(hd[2]);
    const float h3 = lo2(hd[3]), h4 = lo2(hd[4]);
    float acc = b_out[0];
    acc = fmaf(h0, W_out[0],
          fmaf(h1, W_out[1],
          fmaf(h2, W_out[2],
          fmaf(h3, W_out[3],
          fmaf(h4, W_out[4], acc)))));
    out[b] = tanhf(acc);
}

extern "C" void kernel_launch(void* const* d_in, const int* in_sizes, int n_in,
                              void* d_out, int out_size) {
    const float* state = (const float*)d_in[0];   // [B, T, 3]
    const float* W_ih  = (const float*)d_in[1];   // [5, 3]
    const float* W_hh  = (const float*)d_in[2];   // [5, 5]
    const float* b_ih  = (const float*)d_in[3];   // [5]
    const float* b_hh  = (const float*)d_in[4];   // [5]
    const float* W_out = (const float*)d_in[5];   // [1, 5]
    const float* b_out = (const float*)d_in[6];   // [1]

    const int B = out_size;                       // NOUT == 1
    const int T = in_sizes[0] / (B * NIN_);

    const int blocks = (B + 31) / 32;             // 1-warp blocks -> spread across SMs
    rnn_scan_kernel<<<blocks, 32>>>(state, W_ih, W_hh, b_ih, b_hh, W_out, b_out,
                                    (float*)d_out, B, T);
}